// round 17
// baseline (speedup 1.0000x reference)
#include <cuda_runtime.h>
#include <cuda_fp16.h>
#include <cstdint>

// ============================================================================
// IntraSentenceAttention, flash-style, fp16 mma.sync m16n8k16 + ldmatrix,
// one-tile software pipelining (phase B of jt-1, then phase A of jt).
// SINGLE KERNEL: fp32->fp16 conversion is folded into tile staging
// (LDG float4 -> cvt -> STS.64), eliminating the separate prepass and its
// 24 MB of HBM traffic. Mask dtype is detected per-CTA (same classification
// as the old global detector; warp ballots + per-warp smem slots, no atomics).
// Epilogue in the exp2 domain with BLOCK-UNIFORM tile specialization
// (per-warp thresholds spill pk to local memory -- R15):
//   j0 <= i0-73  : dist ≡ 10      -> 2 ops/element
//   j0 >= i0+117 : dist = i-j     -> 3 ops/element (no clamp)
//   otherwise    : general clamp  -> 4 ops/element
// B=32, T=1024, D=128. CTA 128 i-rows, 16 j-tiles of 64, 256 thr / 8 warps,
// 2 CTAs/SM. Xj triple-buffered (STS ordered by the per-tile __syncthreads).
// ============================================================================

namespace {
constexpr int Bb = 32, Tt = 1024, Dd = 128;
constexpr int TM = 128, TN = 64;
constexpr int NJT = Tt / TN;             // 16
constexpr float EPSF = 1e-7f;
constexpr float NEG_INF = -1e30f;
constexpr float L2E = 1.44269504088896f; // log2(e)
constexpr float C10 = 14.4269504088896f; // 10*log2(e)

constexpr int PX = 272;                  // Xi/Xj row pitch bytes, ≡16 mod 128
constexpr int XJSZ = TN * PX;            // 17408

// SMEM byte offsets
constexpr int SM_XI  = 0;                        // 128*272 = 34816
constexpr int SM_XJ  = 34816;                    // 3 x 17408 = 52224
constexpr int SM_LM  = 87040;                    // 1024 f log-mask (4 KB)
constexpr int SM_RP  = 91136;                    // 128 f (aliased: flags at start)
constexpr int SM_INV = 91648;                    // 128 f
constexpr int SMEM_BYTES = 92160;                // 2 CTAs/SM
}

__device__ __forceinline__ float get_mask(const void* m, int idx, int mode) {
    if (mode == 1) return ((const int*)m)[idx] ? 1.0f : 0.0f;
    if (mode == 2) return ((const float*)m)[idx];
    return ((const unsigned char*)m)[idx] ? 1.0f : 0.0f;
}

__device__ __forceinline__ uint32_t smem_u32(const void* p) {
    uint32_t a;
    asm("{ .reg .u64 t; cvta.to.shared.u64 t, %1; cvt.u32.u64 %0, t; }" : "=r"(a) : "l"(p));
    return a;
}
__device__ __forceinline__ void ldsm4(uint32_t r[4], uint32_t a) {
    asm volatile("ldmatrix.sync.aligned.m8n8.x4.shared.b16 {%0,%1,%2,%3}, [%4];"
                 : "=r"(r[0]), "=r"(r[1]), "=r"(r[2]), "=r"(r[3]) : "r"(a));
}
__device__ __forceinline__ void ldsm4t(uint32_t r[4], uint32_t a) {
    asm volatile("ldmatrix.sync.aligned.m8n8.x4.trans.shared.b16 {%0,%1,%2,%3}, [%4];"
                 : "=r"(r[0]), "=r"(r[1]), "=r"(r[2]), "=r"(r[3]) : "r"(a));
}
__device__ __forceinline__ void mma_f16(float d[4], uint32_t a0, uint32_t a1,
                                        uint32_t a2, uint32_t a3,
                                        uint32_t b0, uint32_t b1) {
    asm volatile(
        "mma.sync.aligned.m16n8k16.row.col.f32.f16.f16.f32 "
        "{%0,%1,%2,%3}, {%4,%5,%6,%7}, {%8,%9}, {%0,%1,%2,%3};"
        : "+f"(d[0]), "+f"(d[1]), "+f"(d[2]), "+f"(d[3])
        : "r"(a0), "r"(a1), "r"(a2), "r"(a3), "r"(b0), "r"(b1));
}
__device__ __forceinline__ float ex2f(float v) {
    float r;
    asm("ex2.approx.ftz.f32 %0, %1;" : "=f"(r) : "f"(v));
    return r;
}
// convert one float4 to packed half2x2 and store 8B to SMEM
__device__ __forceinline__ void cvt_sts8(char* dst, float4 v) {
    __half2 h0 = __floats2half2_rn(v.x, v.y);
    __half2 h1 = __floats2half2_rn(v.z, v.w);
    *(uint2*)dst = make_uint2(*(const uint32_t*)&h0, *(const uint32_t*)&h1);
}

// ---------------------------------------------------------------- main kernel
__global__ __launch_bounds__(256, 2)
void attn_mma(const float* __restrict__ x, const void* __restrict__ mask,
              float* __restrict__ out) {
    extern __shared__ char sm[];
    const uint32_t sb = smem_u32(sm);

    const int tid  = threadIdx.x;
    const int w    = tid >> 5, lane = tid & 31;
    const int qrow = lane >> 2;       // 0..7
    const int qk   = lane & 3;        // 0..3
    const int arow0 = w * 16;         // this warp's 16-row band

    const int b  = blockIdx.y;
    const int i0 = blockIdx.x * TM;

    // ldmatrix lane-address offsets (bytes; per-ks/nb terms added at use)
    const int l7 = lane & 7, l8 = (lane >> 3) & 1, l16 = (lane >> 4) & 1;
    const uint32_t offA_xi = (uint32_t)((arow0 + l7 + 8 * l8) * PX + l16 * 16);
    const uint32_t offB_A  = (uint32_t)((l7 + 8 * l16) * PX + l8 * 16);
    const uint32_t offB_B  = (uint32_t)((l7 + 8 * l8) * PX + (8 * l16) * 2);

    float* sLM = (float*)(sm + SM_LM);
    int* sFLG  = (int*)(sm + SM_RP);  // aliased: flags at start, RP at end

    // ---- prologue: stage Xi + tile-0 Xj from fp32 (LDG->cvt->STS),
    //      and scan the mask words for dtype detection (overlapped) --------
    {
        const float* xb = x + (size_t)b * Tt * Dd;
        // Xi: thread -> row tid>>1, 16 float4 chunks, in 2 batches of 8
        const int xr = tid >> 1;
        const float* srcI = xb + (size_t)(i0 + xr) * Dd;
        char* dstI = sm + SM_XI + xr * PX;
        #pragma unroll
        for (int hB = 0; hB < 2; hB++) {
            float4 v[8];
            #pragma unroll
            for (int k = 0; k < 8; k++) {
                const int c = (tid & 1) + 2 * (8 * hB + k);
                v[k] = *(const float4*)(srcI + 4 * c);
            }
            #pragma unroll
            for (int k = 0; k < 8; k++) {
                const int c = (tid & 1) + 2 * (8 * hB + k);
                cvt_sts8(dstI + 8 * c, v[k]);
            }
        }
        // Xj tile 0: thread -> row tid>>2, 8 float4 chunks, 2 batches of 4
        const int jr = tid >> 2;
        const float* srcJ = xb + (size_t)jr * Dd;
        char* dstJ = sm + SM_XJ + jr * PX;
        #pragma unroll
        for (int hB = 0; hB < 2; hB++) {
            float4 v[4];
            #pragma unroll
            for (int k = 0; k < 4; k++) {
                const int c = (tid & 3) + 4 * (4 * hB + k);
                v[k] = *(const float4*)(srcJ + 4 * c);
            }
            #pragma unroll
            for (int k = 0; k < 4; k++) {
                const int c = (tid & 3) + 4 * (4 * hB + k);
                cvt_sts8(dstJ + 8 * c, v[k]);
            }
        }
        // mask dtype scan: same 8192 words the old global detector read
        const unsigned int* mw = (const unsigned int*)mask;
        int not_int = 0, not_flt = 0;
        #pragma unroll
        for (int k = 0; k < 32; k++) {
            unsigned wv = mw[tid + 256 * k];
            if (wv > 1u) not_int = 1;
            if (wv != 0u && wv != 0x3F800000u) not_flt = 1;
        }
        const unsigned bi = __ballot_sync(0xffffffffu, not_int);
        const unsigned bf = __ballot_sync(0xffffffffu, not_flt);
        if (lane == 0) sFLG[w] = (bi ? 1 : 0) | (bf ? 2 : 0);
    }
    __syncthreads();   // flags + Xi + tile-0 visible

    int fl = 0;
    #pragma unroll
    for (int k = 0; k < 8; k++) fl |= sFLG[k];
    const int mode = (!(fl & 1)) ? 1 : ((!(fl & 2)) ? 2 : 0);

    #pragma unroll
    for (int e = 0; e < 4; e++) {
        const int t = tid + 256 * e;
        sLM[t] = (get_mask(mask, b * Tt + t, mode) != 0.0f) ? 0.0f : NEG_INF;
    }
    __syncthreads();   // LM table visible

    float acc[16][4];                 // O: 16 rows x 128 cols per warp
    #pragma unroll
    for (int nf = 0; nf < 16; nf++)
        #pragma unroll
        for (int c = 0; c < 4; c++) acc[nf][c] = 0.0f;
    float rsum[2] = {0.f, 0.f};       // rows qrow, qrow+8

    uint32_t pkp01[8], pkp23[8];      // P fragments (phase-B A-operand)
    const float qk2f = (float)(2 * qk);

    // staging helpers (Xj tile jn from fp32, two 4-float4 batches)
    const int st_jr = tid >> 2;
    const int st_c0 = tid & 3;
    const float* xb = x + (size_t)b * Tt * Dd;

    auto ldg_batch = [&](int jn, int hB, float4 v[4]) {
        const float* src = xb + (size_t)(jn * TN + st_jr) * Dd;
        #pragma unroll
        for (int k = 0; k < 4; k++)
            v[k] = *(const float4*)(src + 4 * (st_c0 + 4 * (4 * hB + k)));
    };
    auto sts_batch = [&](int jn, int hB, const float4 v[4]) {
        char* dst = sm + SM_XJ + (jn % 3) * XJSZ + st_jr * PX;
        #pragma unroll
        for (int k = 0; k < 4; k++)
            cvt_sts8(dst + 8 * (st_c0 + 4 * (4 * hB + k)), v[k]);
    };

    // phase A: S = Xi.Xj^T for tile jt (accumulators in s)
    auto phaseA = [&](int jt, float s[8][4]) {
        const uint32_t xjb = sb + SM_XJ + (jt % 3) * XJSZ;
        #pragma unroll
        for (int ks = 0; ks < Dd / 16; ++ks) {
            uint32_t a[4];
            ldsm4(a, sb + SM_XI + offA_xi + ks * 32);
            #pragma unroll
            for (int nb = 0; nb < 4; nb++) {
                uint32_t bb[4];
                ldsm4(bb, xjb + offB_A + nb * 16 * PX + ks * 32);
                mma_f16(s[2 * nb],     a[0], a[1], a[2], a[3], bb[0], bb[1]);
                mma_f16(s[2 * nb + 1], a[0], a[1], a[2], a[3], bb[2], bb[3]);
            }
        }
    };

    // epilogue: P = ex2(s*L2E + distL + lmL), block-uniform specialization;
    // writes packed fp16 OVER pkp (fully consumed by the preceding phase B).
    auto epilogue = [&](int jt, float s[8][4]) {
        const int j0 = jt * TN;
        const float* lmj = sLM + j0;
        if (j0 <= i0 - 73) {
            #pragma unroll
            for (int nf = 0; nf < 8; nf++) {
                const float2 lm = *(const float2*)(lmj + nf * 8 + 2 * qk);
                const float c0 = lm.x + C10, c1 = lm.y + C10;
                float p0 = ex2f(fmaf(s[nf][0], L2E, c0));
                float p1 = ex2f(fmaf(s[nf][1], L2E, c1));
                float p2 = ex2f(fmaf(s[nf][2], L2E, c0));
                float p3 = ex2f(fmaf(s[nf][3], L2E, c1));
                rsum[0] += p0 + p1;
                rsum[1] += p2 + p3;
                __half2 h01 = __floats2half2_rn(p0, p1);
                __half2 h23 = __floats2half2_rn(p2, p3);
                pkp01[nf] = *(const uint32_t*)&h01;
                pkp23[nf] = *(const uint32_t*)&h23;
            }
        } else if (j0 >= i0 + 117) {
            const float fqL = ((float)(i0 + arow0 + qrow - j0) - qk2f) * L2E;
            #pragma unroll
            for (int nf = 0; nf < 8; nf++) {
                const float2 lm = *(const float2*)(lmj + nf * 8 + 2 * qk);
                const float dL = fqL - (float)(nf * 8) * L2E;
                const float a0 = dL + lm.x,             a1 = dL - L2E + lm.y;
                const float a2 = dL + 8.f * L2E + lm.x, a3 = dL + 7.f * L2E + lm.y;
                float p0 = ex2f(fmaf(s[nf][0], L2E, a0));
                float p1 = ex2f(fmaf(s[nf][1], L2E, a1));
                float p2 = ex2f(fmaf(s[nf][2], L2E, a2));
                float p3 = ex2f(fmaf(s[nf][3], L2E, a3));
                rsum[0] += p0 + p1;
                rsum[1] += p2 + p3;
                __half2 h01 = __floats2half2_rn(p0, p1);
                __half2 h23 = __floats2half2_rn(p2, p3);
                pkp01[nf] = *(const uint32_t*)&h01;
                pkp23[nf] = *(const uint32_t*)&h23;
            }
        } else {
            const float fqL = ((float)(i0 + arow0 + qrow - j0) - qk2f) * L2E;
            #pragma unroll
            for (int nf = 0; nf < 8; nf++) {
                const float2 lm = *(const float2*)(lmj + nf * 8 + 2 * qk);
                const float dL = fqL - (float)(nf * 8) * L2E;
                const float m0 = fminf(dL,             C10) + lm.x;
                const float m1 = fminf(dL - L2E,       C10) + lm.y;
                const float m2 = fminf(dL + 8.f * L2E, C10) + lm.x;
                const float m3 = fminf(dL + 7.f * L2E, C10) + lm.y;
                float p0 = ex2f(fmaf(s[nf][0], L2E, m0));
                float p1 = ex2f(fmaf(s[nf][1], L2E, m1));
                float p2 = ex2f(fmaf(s[nf][2], L2E, m2));
                float p3 = ex2f(fmaf(s[nf][3], L2E, m3));
                rsum[0] += p0 + p1;
                rsum[1] += p2 + p3;
                __half2 h01 = __floats2half2_rn(p0, p1);
                __half2 h23 = __floats2half2_rn(p2, p3);
                pkp01[nf] = *(const uint32_t*)&h01;
                pkp23[nf] = *(const uint32_t*)&h23;
            }
        }
    };

    // phase B: O += P(prev tile) . Xj(prev tile); A-operand from pk registers
    auto phaseB = [&](int jtprev) {
        const uint32_t xjb = sb + SM_XJ + (jtprev % 3) * XJSZ;
        #pragma unroll
        for (int ks = 0; ks < TN / 16; ++ks) {
            const uint32_t a0 = pkp01[2 * ks], a1 = pkp23[2 * ks];
            const uint32_t a2 = pkp01[2 * ks + 1], a3 = pkp23[2 * ks + 1];
            #pragma unroll
            for (int nb = 0; nb < 8; nb++) {
                uint32_t bb[4];
                ldsm4t(bb, xjb + offB_B + nb * 32 + ks * 16 * PX);
                mma_f16(acc[2 * nb],     a0, a1, a2, a3, bb[0], bb[1]);
                mma_f16(acc[2 * nb + 1], a0, a1, a2, a3, bb[2], bb[3]);
            }
        }
    };

    // ---- pipelined main loop (staging interleaved with compute) ----
    {
        // tile 0: no phase B yet; stage tile 1 around phase A
        float4 v[4];
        ldg_batch(1, 0, v);
        float s[8][4];
        #pragma unroll
        for (int nf = 0; nf < 8; nf++)
            #pragma unroll
            for (int c = 0; c < 4; c++) s[nf][c] = 0.0f;
        sts_batch(1, 0, v);
        ldg_batch(1, 1, v);
        phaseA(0, s);
        sts_batch(1, 1, v);
        epilogue(0, s);
    }

    for (int jt = 1; jt < NJT; ++jt) {
        __syncthreads();   // tile jt visible; readers of buf (jt+1)%3 done
        const bool stage = (jt + 1 < NJT);
        float4 v[4];
        if (stage) ldg_batch(jt + 1, 0, v);

        phaseB(jt - 1);    // consumes pkp

        if (stage) { sts_batch(jt + 1, 0, v); ldg_batch(jt + 1, 1, v); }

        float s[8][4];
        #pragma unroll
        for (int nf = 0; nf < 8; nf++)
            #pragma unroll
            for (int c = 0; c < 4; c++) s[nf][c] = 0.0f;
        phaseA(jt, s);

        if (stage) sts_batch(jt + 1, 1, v);

        epilogue(jt, s);   // overwrites pkp in place
    }
    phaseB(NJT - 1);       // drain

    // ---- row-sum reduction + inverse (each row owned by exactly one warp) ----
    float* sRP  = (float*)(sm + SM_RP);
    float* sInv = (float*)(sm + SM_INV);
    __syncthreads();       // all warps past the loop before RP overwrites flags
    #pragma unroll
    for (int rh = 0; rh < 2; rh++) {
        float vv = rsum[rh];
        vv += __shfl_xor_sync(0xffffffffu, vv, 1);
        vv += __shfl_xor_sync(0xffffffffu, vv, 2);
        if (qk == 0) sRP[arow0 + rh * 8 + qrow] = vv;
    }
    __syncthreads();
    if (tid < TM)
        sInv[tid] = ((sLM[i0 + tid] == 0.0f) ? 1.0f : 0.0f) / (sRP[tid] + EPSF);
    __syncthreads();

    // ---- write O ----
    {
        const int rl0 = arow0 + qrow;
        const float inv0 = sInv[rl0], inv1 = sInv[rl0 + 8];
        float* o0 = out + ((size_t)b * Tt + i0 + rl0) * Dd;
        float* o1 = o0 + 8 * Dd;
        #pragma unroll
        for (int nf = 0; nf < 16; nf++) {
            const int cl = nf * 8 + 2 * qk;
            *(float2*)(o0 + cl) = make_float2(acc[nf][0] * inv0, acc[nf][1] * inv0);
            *(float2*)(o1 + cl) = make_float2(acc[nf][2] * inv1, acc[nf][3] * inv1);
        }
    }
}

extern "C" void kernel_launch(void* const* d_in, const int* in_sizes, int n_in,
                              void* d_out, int out_size) {
    const float* x   = (const float*)d_in[0];
    const void* mask = d_in[1];
    float* out       = (float*)d_out;

    cudaFuncSetAttribute(attn_mma, cudaFuncAttributeMaxDynamicSharedMemorySize, SMEM_BYTES);

    dim3 grid(Tt / TM, Bb);
    attn_mma<<<grid, 256, SMEM_BYTES>>>(x, mask, out);
}